// round 14
// baseline (speedup 1.0000x reference)
#include <cuda_runtime.h>
#include <cstdint>

// Problem constants
#define BB   8
#define LL   200
#define DD   128
#define HH   4
#define HS   32
#define HB   (HH*BB)        // 32
#define NROW (HB*LL)        // 6400
#define CAP  204

// Scratch (device globals; no allocation allowed)
__device__ float g_ad[BB*LL*DD];       // a in [b][i][d]
__device__ float g_bd[BB*LL*DD];       // b in [b][j][d]
__device__ float g_sv[HB*LL*HS];       // sv in [bh][j][hs]
__device__ float g_raw[NROW*LL];       // only j<=i valid
__device__ int   g_cnt[NROW];
__device__ int   g_list[NROW*CAP];

// ---------------------------------------------------------------------------
// Stage 1: a/b projections (sv lives in k_rawtop's grid). UNCHANGED from R13.
// ---------------------------------------------------------------------------
__global__ void __launch_bounds__(64) k_gemm(
                       const float* __restrict__ seqs,
                       const float* __restrict__ w1, const float* __restrict__ b1,
                       const float* __restrict__ w2, const float* __restrict__ b2)
{
    __shared__ float st[128 * 32];   // [k][r swizzled] 16 KB
    __shared__ float wt[128 * 32];   // [k][c swizzled] 16 KB

    const int ct = blockIdx.y;
    const int m  = ct >> 2;                 // matrix 0..1
    const int o0 = (ct & 3) * 32;           // col base within matrix
    const float* w    = (m == 0) ? w1 : w2;
    const float* bias = (m == 0) ? b1 : b2;

    const int row0 = blockIdx.x * 32;
    const int tid  = threadIdx.x;

    {
        int idx = (blockIdx.y * 50 + blockIdx.x) * 64 + tid;
        if (idx < NROW) g_cnt[idx] = 0;
    }

#pragma unroll
    for (int it = 0; it < 16; it++) {
        int idx = it * 64 + tid;
        int r = idx & 31, k = (idx >> 5) * 4;
        float4 v = *(const float4*)&seqs[(row0 + r) * DD + k];
        st[(k + 0) * 32 + (r ^ (((k + 0) & 7) << 2))] = v.x;
        st[(k + 1) * 32 + (r ^ (((k + 1) & 7) << 2))] = v.y;
        st[(k + 2) * 32 + (r ^ (((k + 2) & 7) << 2))] = v.z;
        st[(k + 3) * 32 + (r ^ (((k + 3) & 7) << 2))] = v.w;
    }
#pragma unroll
    for (int it = 0; it < 16; it++) {
        int idx = it * 64 + tid;
        int c = idx & 31, k = (idx >> 5) * 4;
        float4 v = *(const float4*)&w[(o0 + c) * DD + k];
        wt[(k + 0) * 32 + (c ^ (((k + 0) & 7) << 2))] = v.x;
        wt[(k + 1) * 32 + (c ^ (((k + 1) & 7) << 2))] = v.y;
        wt[(k + 2) * 32 + (c ^ (((k + 2) & 7) << 2))] = v.z;
        wt[(k + 3) * 32 + (c ^ (((k + 3) & 7) << 2))] = v.w;
    }
    __syncthreads();

    const int rg = tid >> 3;       // 0..7
    const int cg = tid & 7;        // 0..7
    const int r0 = rg * 4, c0 = cg * 4;

    float acc[4][4];
#pragma unroll
    for (int r = 0; r < 4; r++)
#pragma unroll
        for (int c = 0; c < 4; c++) acc[r][c] = 0.f;

#pragma unroll 8
    for (int k = 0; k < DD; k++) {
        const int sw = (k & 7) << 2;
        float4 s4 = *(const float4*)&st[k * 32 + (r0 ^ sw)];
        float4 w4 = *(const float4*)&wt[k * 32 + (c0 ^ sw)];
        float sv[4] = {s4.x, s4.y, s4.z, s4.w};
        float wv[4] = {w4.x, w4.y, w4.z, w4.w};
#pragma unroll
        for (int r = 0; r < 4; r++)
#pragma unroll
            for (int c = 0; c < 4; c++)
                acc[r][c] += sv[r] * wv[c];
    }

    float bi[4];
#pragma unroll
    for (int c = 0; c < 4; c++) bi[c] = bias[o0 + c0 + c];

    float* dst = (m == 0) ? g_ad : g_bd;
#pragma unroll
    for (int r = 0; r < 4; r++) {
        int n = row0 + r0 + r;
        float4 v = {acc[r][0] + bi[0], acc[r][1] + bi[1],
                    acc[r][2] + bi[2], acc[r][3] + bi[3]};
        *(float4*)&dst[n * DD + o0 + c0] = v;
    }
}

// ---------------------------------------------------------------------------
// Stage 2: heterogeneous grid, 1D 850 blocks x 128 threads.
//   blocks 0..49   : sv projection (hidden under rawtop's memory phase).
//   blocks 50..849 : rawtop for (b, i0, i0+1) — i-PAIRED: b[j] loaded once
//                    per pair (halves g_bd L2 traffic); tm for both i's.
//                    Pair index scrambled (29p mod 100) for SM balance.
//                    Per-(i,j) arithmetic BIT-IDENTICAL to R8/R13: 8-channel
//                    float4 partials, xor-1/xor-2 tree, ascending-j strict->
//                    insertion; exact lax.top_k merge (value desc, index asc)
//                    + masked-zero candidates; symmetrized list push.
// ---------------------------------------------------------------------------
__global__ void __launch_bounds__(128) k_rawtop(
    const float* __restrict__ tm,
    const float* __restrict__ seqs,
    const float* __restrict__ w3, const float* __restrict__ b3)
{
    __shared__ float s_seq[32 * DD];     // 16 KB (sv blocks)
    __shared__ float tvs[4][2][2][HH][3];
    __shared__ int   tjs[4][2][2][HH][3];

    const int bx = blockIdx.x;
    const int tid = threadIdx.x;

    if (bx < 50) {
        // ---- sv projection block: rows row0..row0+31, all 128 cols ----
        const int row0 = bx * 32;
#pragma unroll
        for (int it = 0; it < 32; it++) {
            int idx = it * 128 + tid;
            int r = idx >> 7, k = idx & 127;
            s_seq[r * DD + k] = seqs[(row0 + r) * DD + k];
        }
        __syncthreads();

        const int o = tid;
        const float bb = b3[o];
        float acc[32];
#pragma unroll
        for (int r = 0; r < 32; r++) acc[r] = 0.f;

        const float4* w4 = (const float4*)(w3 + o * DD);
        for (int k4 = 0; k4 < 32; k4++) {
            float4 wv = w4[k4];
#pragma unroll
            for (int r = 0; r < 32; r++) {
                float4 s4 = *(const float4*)&s_seq[r * DD + k4 * 4];
                acc[r] += s4.x * wv.x + s4.y * wv.y + s4.z * wv.z + s4.w * wv.w;
            }
        }

        const int h = o >> 5, hs = o & 31;
#pragma unroll
        for (int r = 0; r < 32; r++) {
            int n = row0 + r;
            int b_ = n / LL, i_ = n % LL;
            g_sv[((h * BB + b_) * LL + i_) * HS + hs] = acc[r] + bb;
        }
        return;
    }

    // ---- rawtop block: (b, i0, i1) ----
    const int bxr = bx - 50;
    const int b   = bxr / 100;
    const int p   = bxr % 100;
    const int i0  = 2 * ((29 * p) % 100);   // load-balance scramble
    const int i1  = i0 + 1;
    const int w = tid >> 5, lane = tid & 31;
    const int half = lane >> 4;
    const int sub  = lane & 15;
    const int h    = sub >> 2;
    const int d0   = sub * 8;

    // a vectors for both i's
    const float4* ap0 = (const float4*)(g_ad + (size_t)(b * LL + i0) * DD + d0);
    const float4* ap1 = (const float4*)(g_ad + (size_t)(b * LL + i1) * DD + d0);
    const float4 aA0 = ap0[0], aB0 = ap0[1];
    const float4 aA1 = ap1[0], aB1 = ap1[1];

    float an0 = aA0.x*aA0.x + aA0.y*aA0.y + aA0.z*aA0.z + aA0.w*aA0.w
              + aB0.x*aB0.x + aB0.y*aB0.y + aB0.z*aB0.z + aB0.w*aB0.w;
    float an1 = aA1.x*aA1.x + aA1.y*aA1.y + aA1.z*aA1.z + aA1.w*aA1.w
              + aB1.x*aB1.x + aB1.y*aB1.y + aB1.z*aB1.z + aB1.w*aB1.w;
    an0 += __shfl_xor_sync(0xffffffffu, an0, 1);
    an1 += __shfl_xor_sync(0xffffffffu, an1, 1);
    an0 += __shfl_xor_sync(0xffffffffu, an0, 2);
    an1 += __shfl_xor_sync(0xffffffffu, an1, 2);
    an0 = sqrtf(an0);
    an1 = sqrtf(an1);

    float v00 = -3.4e38f, v01 = -3.4e38f, v02 = -3.4e38f;
    int   j00 = -1, j01 = -1, j02 = -1;
    float v10 = -3.4e38f, v11 = -3.4e38f, v12 = -3.4e38f;
    int   j10 = -1, j11 = -1, j12 = -1;

    const float* tm0 = tm   + (size_t)(b * LL + i0) * LL * DD + d0;
    const float* tm1 = tm   + (size_t)(b * LL + i1) * LL * DD + d0;
    const float* bp  = g_bd + (size_t)b * LL * DD + d0;
    float* rr0 = g_raw + (size_t)((h * BB + b) * LL + i0) * LL;
    float* rr1 = g_raw + (size_t)((h * BB + b) * LL + i1) * LL;

    for (int jb = 2 * w; jb <= i1; jb += 16) {
        const int jA = jb + half;
        const int jB = jb + 8 + half;
        const bool pA1 = (jA <= i1), pA0 = (jA <= i0);
        const bool pB1 = (jB <= i1), pB0 = (jB <= i0);

        float nA0 = 0.f, dA0 = 0.f, nA1 = 0.f, dA1 = 0.f;
        float nB0 = 0.f, dB0 = 0.f, nB1 = 0.f, dB1 = 0.f;

        if (pA1) {
            const float4* b4 = (const float4*)(bp + (size_t)jA * DD);
            float4 c0v = b4[0], c1 = b4[1];
            if (pA0) {
                const float4* t4 = (const float4*)(tm0 + (size_t)jA * DD);
                float4 t0 = __ldcs(t4), t1 = __ldcs(t4 + 1);
                float sx = t0.x + c0v.x, sy = t0.y + c0v.y, sz = t0.z + c0v.z, sw = t0.w + c0v.w;
                nA0 = aA0.x*sx + aA0.y*sy + aA0.z*sz + aA0.w*sw;
                dA0 = sx*sx + sy*sy + sz*sz + sw*sw;
                sx = t1.x + c1.x; sy = t1.y + c1.y; sz = t1.z + c1.z; sw = t1.w + c1.w;
                nA0 += aB0.x*sx + aB0.y*sy + aB0.z*sz + aB0.w*sw;
                dA0 += sx*sx + sy*sy + sz*sz + sw*sw;
            }
            {
                const float4* t4 = (const float4*)(tm1 + (size_t)jA * DD);
                float4 t0 = __ldcs(t4), t1 = __ldcs(t4 + 1);
                float sx = t0.x + c0v.x, sy = t0.y + c0v.y, sz = t0.z + c0v.z, sw = t0.w + c0v.w;
                nA1 = aA1.x*sx + aA1.y*sy + aA1.z*sz + aA1.w*sw;
                dA1 = sx*sx + sy*sy + sz*sz + sw*sw;
                sx = t1.x + c1.x; sy = t1.y + c1.y; sz = t1.z + c1.z; sw = t1.w + c1.w;
                nA1 += aB1.x*sx + aB1.y*sy + aB1.z*sz + aB1.w*sw;
                dA1 += sx*sx + sy*sy + sz*sz + sw*sw;
            }
        }
        if (pB1) {
            const float4* b4 = (const float4*)(bp + (size_t)jB * DD);
            float4 c0v = b4[0], c1 = b4[1];
            if (pB0) {
                const float4* t4 = (const float4*)(tm0 + (size_t)jB * DD);
                float4 t0 = __ldcs(t4), t1 = __ldcs(t4 + 1);
                float sx = t0.x + c0v.x, sy = t0.y + c0v.y, sz = t0.z + c0v.z, sw = t0.w + c0v.w;
                nB0 = aA0.x*sx + aA0.y*sy + aA0.z*sz + aA0.w*sw;
                dB0 = sx*sx + sy*sy + sz*sz + sw*sw;
                sx = t1.x + c1.x; sy = t1.y + c1.y; sz = t1.z + c1.z; sw = t1.w + c1.w;
                nB0 += aB0.x*sx + aB0.y*sy + aB0.z*sz + aB0.w*sw;
                dB0 += sx*sx + sy*sy + sz*sz + sw*sw;
            }
            {
                const float4* t4 = (const float4*)(tm1 + (size_t)jB * DD);
                float4 t0 = __ldcs(t4), t1 = __ldcs(t4 + 1);
                float sx = t0.x + c0v.x, sy = t0.y + c0v.y, sz = t0.z + c0v.z, sw = t0.w + c0v.w;
                nB1 = aA1.x*sx + aA1.y*sy + aA1.z*sz + aA1.w*sw;
                dB1 = sx*sx + sy*sy + sz*sz + sw*sw;
                sx = t1.x + c1.x; sy = t1.y + c1.y; sz = t1.z + c1.z; sw = t1.w + c1.w;
                nB1 += aB1.x*sx + aB1.y*sy + aB1.z*sz + aB1.w*sw;
                dB1 += sx*sx + sy*sy + sz*sz + sw*sw;
            }
        }

        nA0 += __shfl_xor_sync(0xffffffffu, nA0, 1);
        dA0 += __shfl_xor_sync(0xffffffffu, dA0, 1);
        nA1 += __shfl_xor_sync(0xffffffffu, nA1, 1);
        dA1 += __shfl_xor_sync(0xffffffffu, dA1, 1);
        nB0 += __shfl_xor_sync(0xffffffffu, nB0, 1);
        dB0 += __shfl_xor_sync(0xffffffffu, dB0, 1);
        nB1 += __shfl_xor_sync(0xffffffffu, nB1, 1);
        dB1 += __shfl_xor_sync(0xffffffffu, dB1, 1);
        nA0 += __shfl_xor_sync(0xffffffffu, nA0, 2);
        dA0 += __shfl_xor_sync(0xffffffffu, dA0, 2);
        nA1 += __shfl_xor_sync(0xffffffffu, nA1, 2);
        dA1 += __shfl_xor_sync(0xffffffffu, dA1, 2);
        nB0 += __shfl_xor_sync(0xffffffffu, nB0, 2);
        dB0 += __shfl_xor_sync(0xffffffffu, dB0, 2);
        nB1 += __shfl_xor_sync(0xffffffffu, nB1, 2);
        dB1 += __shfl_xor_sync(0xffffffffu, dB1, 2);

        if ((lane & 3) == 0) {
            if (pA0) {
                float v = nA0 / (an0 * sqrtf(dA0) + 1e-6f);
                rr0[jA] = v;
                if (v > v00)      { v02=v01; j02=j01; v01=v00; j01=j00; v00=v; j00=jA; }
                else if (v > v01) { v02=v01; j02=j01; v01=v;  j01=jA; }
                else if (v > v02) { v02=v;  j02=jA; }
            }
            if (pA1) {
                float v = nA1 / (an1 * sqrtf(dA1) + 1e-6f);
                rr1[jA] = v;
                if (v > v10)      { v12=v11; j12=j11; v11=v10; j11=j10; v10=v; j10=jA; }
                else if (v > v11) { v12=v11; j12=j11; v11=v;  j11=jA; }
                else if (v > v12) { v12=v;  j12=jA; }
            }
            if (pB0) {
                float v = nB0 / (an0 * sqrtf(dB0) + 1e-6f);
                rr0[jB] = v;
                if (v > v00)      { v02=v01; j02=j01; v01=v00; j01=j00; v00=v; j00=jB; }
                else if (v > v01) { v02=v01; j02=j01; v01=v;  j01=jB; }
                else if (v > v02) { v02=v;  j02=jB; }
            }
            if (pB1) {
                float v = nB1 / (an1 * sqrtf(dB1) + 1e-6f);
                rr1[jB] = v;
                if (v > v10)      { v12=v11; j12=j11; v11=v10; j11=j10; v10=v; j10=jB; }
                else if (v > v11) { v12=v11; j12=j11; v11=v;  j11=jB; }
                else if (v > v12) { v12=v;  j12=jB; }
            }
        }
    }

    if ((lane & 3) == 0) {
        tvs[w][half][0][h][0] = v00; tjs[w][half][0][h][0] = j00;
        tvs[w][half][0][h][1] = v01; tjs[w][half][0][h][1] = j01;
        tvs[w][half][0][h][2] = v02; tjs[w][half][0][h][2] = j02;
        tvs[w][half][1][h][0] = v10; tjs[w][half][1][h][0] = j10;
        tvs[w][half][1][h][1] = v11; tjs[w][half][1][h][1] = j11;
        tvs[w][half][1][h][2] = v12; tjs[w][half][1][h][2] = j12;
    }
    __syncthreads();

    // merge + list push: thread t < 8 handles (i_loc = t>>2, head = t&3)
    if (tid < 8) {
        const int iloc = tid >> 2, hh = tid & 3;
        const int i = i0 + iloc;
        float V0 = -3.4e38f, V1 = -3.4e38f, V2 = -3.4e38f;
        int   I0 = 0x7fffffff, I1 = 0x7fffffff, I2 = 0x7fffffff;
        auto ins = [&](float v, int j) {
            if (j < 0) return;
            if (v > V0 || (v == V0 && j < I0)) { V2=V1;I2=I1; V1=V0;I1=I0; V0=v;I0=j; }
            else if (v > V1 || (v == V1 && j < I1)) { V2=V1;I2=I1; V1=v;I1=j; }
            else if (v > V2 || (v == V2 && j < I2)) { V2=v;I2=j; }
        };
#pragma unroll
        for (int ww = 0; ww < 4; ww++)
#pragma unroll
            for (int hf = 0; hf < 2; hf++)
#pragma unroll
                for (int qq = 0; qq < 3; qq++)
                    ins(tvs[ww][hf][iloc][hh][qq], tjs[ww][hf][iloc][hh][qq]);
#pragma unroll
        for (int z = 1; z <= 3; z++) {
            int jz = i + z;
            if (jz < LL) ins(0.0f, jz);   // masked zeros (index-asc ties)
        }
        const int bh = hh * BB + b;
        const int rg = bh * LL + i;
        int sel[3] = {I0, I1, I2};
#pragma unroll
        for (int s = 0; s < 3; s++) {
            int t = sel[s];
            if (t <= i) {
                int pq = atomicAdd(&g_cnt[rg], 1);
                if (pq < CAP) g_list[rg * CAP + pq] = t;
            } else {
                int tg = bh * LL + t;
                int pq = atomicAdd(&g_cnt[tg], 1);
                if (pq < CAP) g_list[tg * CAP + pq] = i;
            }
        }
    }
}

// ---------------------------------------------------------------------------
// Stage 3 (fused sparse gather + LayerNorm): UNCHANGED from R13.
// ---------------------------------------------------------------------------
__global__ void k_gather_ln(const float* __restrict__ tm,
                            const float* __restrict__ gam,
                            const float* __restrict__ bet,
                            float* __restrict__ out_ln,
                            float* __restrict__ out_tio)
{
    const int i = blockIdx.x, b = blockIdx.y;
    const int tid = threadIdx.x;
    const int h = tid >> 5, lane = tid & 31;
    const int bh = h * BB + b;
    const int rg = bh * LL + i;

    __shared__ unsigned bm[HH][7];
    __shared__ float red[4];

    if (lane < 7) bm[h][lane] = 0u;
    __syncwarp();

    const int n = min(g_cnt[rg], CAP);
    for (int c = lane; c < n; c += 32) {
        int j = g_list[rg * CAP + c];
        atomicOr(&bm[h][j >> 5], 1u << (j & 31));
    }
    __syncwarp();

    float ao = 0.f, at = 0.f;
    float ao2 = 0.f, at2 = 0.f;
    const float* rrow = g_raw + (size_t)rg * LL;
    const float* tmb  = tm + (size_t)(b * LL + i) * LL * DD + h * HS + lane;
    const float* svb  = g_sv + (size_t)bh * LL * HS + lane;

    for (int w = 0; w < 7; w++) {
        unsigned m = bm[h][w];
        while (m) {
            int b1 = __ffs(m) - 1;  m &= m - 1;
            int b2 = -1;
            if (m) { b2 = __ffs(m) - 1; m &= m - 1; }
            int ja = w * 32 + b1;
            float sga = rrow[ja];
            float sv_a = svb[ja * HS];
            float tm_a = tmb[(size_t)ja * DD];
            if (b2 >= 0) {
                int jb2 = w * 32 + b2;
                float sgb = rrow[jb2];
                ao2 += sgb * svb[jb2 * HS];
                at2 += sgb * tmb[(size_t)jb2 * DD];
            }
            ao += sga * sv_a;
            at += sga * tm_a;
        }
    }
    ao += ao2;
    at += at2;

    const int d = tid;                 // d = h*HS + lane
    out_tio[(b * LL + i) * DD + d] = at;

    // LayerNorm over the 128 'ao' values
    float s = ao;
#pragma unroll
    for (int k = 16; k; k >>= 1) s += __shfl_xor_sync(0xffffffffu, s, k);
    if (lane == 0) red[h] = s;
    __syncthreads();
    float mu = (red[0] + red[1] + red[2] + red[3]) * (1.f / 128.f);
    __syncthreads();

    float dv = ao - mu;
    float s2 = dv * dv;
#pragma unroll
    for (int k = 16; k; k >>= 1) s2 += __shfl_xor_sync(0xffffffffu, s2, k);
    if (lane == 0) red[h] = s2;
    __syncthreads();
    float var = (red[0] + red[1] + red[2] + red[3]) * (1.f / 128.f);

    out_ln[(b * LL + i) * DD + d] = dv / sqrtf(var + 1e-8f) * gam[d] + bet[d];
}

// ---------------------------------------------------------------------------
extern "C" void kernel_launch(void* const* d_in, const int* in_sizes, int n_in,
                              void* d_out, int out_size)
{
    const float* seqs = (const float*)d_in[0];
    // d_in[1] = attention_mask (known causal triu) — unused
    const float* tm   = (const float*)d_in[2];
    const float* w1   = (const float*)d_in[3];
    const float* b1   = (const float*)d_in[4];
    const float* w2   = (const float*)d_in[5];
    const float* b2   = (const float*)d_in[6];
    const float* w3   = (const float*)d_in[7];
    const float* b3   = (const float*)d_in[8];
    const float* lng  = (const float*)d_in[9];
    const float* lnb  = (const float*)d_in[10];

    float* out_ln  = (float*)d_out;
    float* out_tio = out_ln + BB * LL * DD;

    k_gemm     <<<dim3(50, 8),  64>>>(seqs, w1, b1, w2, b2);
    k_rawtop   <<<850,         128>>>(tm, seqs, w3, b3);
    k_gather_ln<<<dim3(LL, BB),128>>>(tm, lng, lnb, out_ln, out_tio);
}

// round 15
// speedup vs baseline: 1.0953x; 1.0953x over previous
#include <cuda_runtime.h>
#include <cstdint>

// Problem constants
#define BB   8
#define LL   200
#define DD   128
#define HH   4
#define HS   32
#define HB   (HH*BB)        // 32
#define NROW (HB*LL)        // 6400
#define CAP  204

// Scratch (device globals; no allocation allowed)
__device__ float g_ad[BB*LL*DD];       // a in [b][i][d]
__device__ float g_bd[BB*LL*DD];       // b in [b][j][d]
__device__ float g_sv[HB*LL*HS];       // sv in [bh][j][hs]
__device__ float g_raw[NROW*LL];       // only j<=i valid
__device__ int   g_cnt[NROW];
__device__ int   g_list[NROW*CAP];

// ---------------------------------------------------------------------------
// Stage 1: a/b projections (sv lives in k_rawtop's grid).
// grid (50 rowtiles of 32, 16 = 2 matrices x 8 coltiles of 16), block 64
// -> 800 blocks = 10.8 warps/SM (2x R13). Tile 32x16, 4x2 per thread.
// st: full-K XOR-swizzled (conflict-free STS + LDS.128, identical to R13).
// wt: [k][c] 16-wide, no swizzle (compute reads = 8 distinct float2 slots,
// conflict-free; staging STS 2-way, negligible).
// Per-output FMA chain = serial k -> a/b BIT-IDENTICAL to R13-passing.
// Also zeroes g_cnt.
// ---------------------------------------------------------------------------
__global__ void __launch_bounds__(64) k_gemm(
                       const float* __restrict__ seqs,
                       const float* __restrict__ w1, const float* __restrict__ b1,
                       const float* __restrict__ w2, const float* __restrict__ b2)
{
    __shared__ float st[128 * 32];   // [k][r swizzled] 16 KB
    __shared__ float wt[128 * 16];   // [k][c]           8 KB

    const int ct = blockIdx.y;
    const int m  = ct >> 3;                 // matrix 0..1
    const int o0 = (ct & 7) * 16;           // col base within matrix
    const float* w    = (m == 0) ? w1 : w2;
    const float* bias = (m == 0) ? b1 : b2;

    const int row0 = blockIdx.x * 32;
    const int tid  = threadIdx.x;

    {
        int idx = (blockIdx.y * 50 + blockIdx.x) * 64 + tid;
        if (idx < NROW) g_cnt[idx] = 0;
    }

    // Stage seqs tile: lane owns row r = idx&31 -> conflict-free STS.
#pragma unroll
    for (int it = 0; it < 16; it++) {
        int idx = it * 64 + tid;
        int r = idx & 31, k = (idx >> 5) * 4;
        float4 v = *(const float4*)&seqs[(row0 + r) * DD + k];
        st[(k + 0) * 32 + (r ^ (((k + 0) & 7) << 2))] = v.x;
        st[(k + 1) * 32 + (r ^ (((k + 1) & 7) << 2))] = v.y;
        st[(k + 2) * 32 + (r ^ (((k + 2) & 7) << 2))] = v.z;
        st[(k + 3) * 32 + (r ^ (((k + 3) & 7) << 2))] = v.w;
    }
    // Stage weight tile: 16 cols x 128 k (512 float4 / 64 thr = 8 iters).
#pragma unroll
    for (int it = 0; it < 8; it++) {
        int idx = it * 64 + tid;
        int c = idx & 15, k = (idx >> 4) * 4;
        float4 v = *(const float4*)&w[(o0 + c) * DD + k];
        wt[(k + 0) * 16 + c] = v.x;
        wt[(k + 1) * 16 + c] = v.y;
        wt[(k + 2) * 16 + c] = v.z;
        wt[(k + 3) * 16 + c] = v.w;
    }
    __syncthreads();

    const int rg = tid >> 3;       // 0..7
    const int cg = tid & 7;        // 0..7
    const int r0 = rg * 4, c0 = cg * 2;

    float acc[4][2];
#pragma unroll
    for (int r = 0; r < 4; r++)
#pragma unroll
        for (int c = 0; c < 2; c++) acc[r][c] = 0.f;

#pragma unroll 8
    for (int k = 0; k < DD; k++) {
        const int sw = (k & 7) << 2;
        float4 s4 = *(const float4*)&st[k * 32 + (r0 ^ sw)];
        float2 w2 = *(const float2*)&wt[k * 16 + c0];
        float sv[4] = {s4.x, s4.y, s4.z, s4.w};
        float wv[2] = {w2.x, w2.y};
#pragma unroll
        for (int r = 0; r < 4; r++)
#pragma unroll
            for (int c = 0; c < 2; c++)
                acc[r][c] += sv[r] * wv[c];
    }

    float bi[2];
#pragma unroll
    for (int c = 0; c < 2; c++) bi[c] = bias[o0 + c0 + c];

    float* dst = (m == 0) ? g_ad : g_bd;
#pragma unroll
    for (int r = 0; r < 4; r++) {
        int n = row0 + r0 + r;
        float2 v = {acc[r][0] + bi[0], acc[r][1] + bi[1]};
        *(float2*)&dst[n * DD + o0 + c0] = v;
    }
}

// ---------------------------------------------------------------------------
// Stage 2: heterogeneous grid, 1D 1650 blocks x 128 threads. UNCHANGED R13.
//   blocks 0..49    : sv projection (hidden under rawtop's memory phase).
//   blocks 50..1649 : rawtop for (b,i), i = (29*bx2) mod 200 scramble.
//                     tm via __ldcs (streaming). EXACT R8-passing arithmetic.
// ---------------------------------------------------------------------------
__global__ void __launch_bounds__(128) k_rawtop(
    const float* __restrict__ tm,
    const float* __restrict__ seqs,
    const float* __restrict__ w3, const float* __restrict__ b3)
{
    __shared__ float s_seq[32 * DD];     // 16 KB (sv blocks)
    __shared__ float tvs[4][2][HH][3];
    __shared__ int   tjs[4][2][HH][3];

    const int bx = blockIdx.x;
    const int tid = threadIdx.x;

    if (bx < 50) {
        // ---- sv projection block: rows row0..row0+31, all 128 cols ----
        const int row0 = bx * 32;
#pragma unroll
        for (int it = 0; it < 32; it++) {
            int idx = it * 128 + tid;
            int r = idx >> 7, k = idx & 127;
            s_seq[r * DD + k] = seqs[(row0 + r) * DD + k];
        }
        __syncthreads();

        const int o = tid;
        const float bb = b3[o];
        float acc[32];
#pragma unroll
        for (int r = 0; r < 32; r++) acc[r] = 0.f;

        const float4* w4 = (const float4*)(w3 + o * DD);
        for (int k4 = 0; k4 < 32; k4++) {
            float4 wv = w4[k4];
#pragma unroll
            for (int r = 0; r < 32; r++) {
                float4 s4 = *(const float4*)&s_seq[r * DD + k4 * 4];
                acc[r] += s4.x * wv.x + s4.y * wv.y + s4.z * wv.z + s4.w * wv.w;
            }
        }

        const int h = o >> 5, hs = o & 31;
#pragma unroll
        for (int r = 0; r < 32; r++) {
            int n = row0 + r;
            int b_ = n / LL, i_ = n % LL;
            g_sv[((h * BB + b_) * LL + i_) * HS + hs] = acc[r] + bb;
        }
        return;
    }

    // ---- rawtop block ----
    const int bxr = bx - 50;
    const int b   = bxr / LL;
    const int bx2 = bxr % LL;
    const int i   = (29 * bx2) % LL;    // load-balance scramble
    const int w = tid >> 5, lane = tid & 31;
    const int half = lane >> 4;
    const int sub  = lane & 15;
    const int h    = sub >> 2;
    const int d0   = sub * 8;

    const float4* ap = (const float4*)(g_ad + (size_t)(b * LL + i) * DD + d0);
    const float4 aA = ap[0], aB = ap[1];
    float an = aA.x*aA.x + aA.y*aA.y + aA.z*aA.z + aA.w*aA.w
             + aB.x*aB.x + aB.y*aB.y + aB.z*aB.z + aB.w*aB.w;
    an += __shfl_xor_sync(0xffffffffu, an, 1);
    an += __shfl_xor_sync(0xffffffffu, an, 2);
    an = sqrtf(an);

    float v0 = -3.4e38f, v1 = -3.4e38f, v2 = -3.4e38f;
    int   j0 = -1, j1 = -1, j2 = -1;

    const float* tmp = tm   + (size_t)(b * LL + i) * LL * DD + d0;
    const float* bp  = g_bd + (size_t)b * LL * DD + d0;
    float* rr = g_raw + (size_t)((h * BB + b) * LL + i) * LL;

    for (int jb = 2 * w; jb <= i; jb += 16) {
        const int jA = jb + half;
        const int jB = jb + 8 + half;
        const bool pA = (jA <= i);
        const bool pB = (jB <= i);

        float numA = 0.f, denA = 0.f, numB = 0.f, denB = 0.f;

        if (pA) {
            const float4* t4 = (const float4*)(tmp + (size_t)jA * DD);
            const float4* b4 = (const float4*)(bp  + (size_t)jA * DD);
            float4 t0 = __ldcs(t4), t1 = __ldcs(t4 + 1);
            float4 c0v = b4[0], c1 = b4[1];
            float sx = t0.x + c0v.x, sy = t0.y + c0v.y, sz = t0.z + c0v.z, sw = t0.w + c0v.w;
            numA = aA.x*sx + aA.y*sy + aA.z*sz + aA.w*sw;
            denA = sx*sx + sy*sy + sz*sz + sw*sw;
            sx = t1.x + c1.x; sy = t1.y + c1.y; sz = t1.z + c1.z; sw = t1.w + c1.w;
            numA += aB.x*sx + aB.y*sy + aB.z*sz + aB.w*sw;
            denA += sx*sx + sy*sy + sz*sz + sw*sw;
        }
        if (pB) {
            const float4* t4 = (const float4*)(tmp + (size_t)jB * DD);
            const float4* b4 = (const float4*)(bp  + (size_t)jB * DD);
            float4 t0 = __ldcs(t4), t1 = __ldcs(t4 + 1);
            float4 c0v = b4[0], c1 = b4[1];
            float sx = t0.x + c0v.x, sy = t0.y + c0v.y, sz = t0.z + c0v.z, sw = t0.w + c0v.w;
            numB = aA.x*sx + aA.y*sy + aA.z*sz + aA.w*sw;
            denB = sx*sx + sy*sy + sz*sz + sw*sw;
            sx = t1.x + c1.x; sy = t1.y + c1.y; sz = t1.z + c1.z; sw = t1.w + c1.w;
            numB += aB.x*sx + aB.y*sy + aB.z*sz + aB.w*sw;
            denB += sx*sx + sy*sy + sz*sz + sw*sw;
        }

        numA += __shfl_xor_sync(0xffffffffu, numA, 1);
        denA += __shfl_xor_sync(0xffffffffu, denA, 1);
        numB += __shfl_xor_sync(0xffffffffu, numB, 1);
        denB += __shfl_xor_sync(0xffffffffu, denB, 1);
        numA += __shfl_xor_sync(0xffffffffu, numA, 2);
        denA += __shfl_xor_sync(0xffffffffu, denA, 2);
        numB += __shfl_xor_sync(0xffffffffu, numB, 2);
        denB += __shfl_xor_sync(0xffffffffu, denB, 2);

        if ((lane & 3) == 0) {
            if (pA) {
                float v = numA / (an * sqrtf(denA) + 1e-6f);
                rr[jA] = v;
                if (v > v0)      { v2=v1; j2=j1; v1=v0; j1=j0; v0=v; j0=jA; }
                else if (v > v1) { v2=v1; j2=j1; v1=v;  j1=jA; }
                else if (v > v2) { v2=v;  j2=jA; }
            }
            if (pB) {
                float v = numB / (an * sqrtf(denB) + 1e-6f);
                rr[jB] = v;
                if (v > v0)      { v2=v1; j2=j1; v1=v0; j1=j0; v0=v; j0=jB; }
                else if (v > v1) { v2=v1; j2=j1; v1=v;  j1=jB; }
                else if (v > v2) { v2=v;  j2=jB; }
            }
        }
    }

    if ((lane & 3) == 0) {
        tvs[w][half][h][0] = v0; tjs[w][half][h][0] = j0;
        tvs[w][half][h][1] = v1; tjs[w][half][h][1] = j1;
        tvs[w][half][h][2] = v2; tjs[w][half][h][2] = j2;
    }
    __syncthreads();

    // merge + list push: thread hh < 4 handles head hh
    if (tid < HH) {
        const int hh = tid;
        float V0 = -3.4e38f, V1 = -3.4e38f, V2 = -3.4e38f;
        int   I0 = 0x7fffffff, I1 = 0x7fffffff, I2 = 0x7fffffff;
        auto ins = [&](float v, int j) {
            if (j < 0) return;
            if (v > V0 || (v == V0 && j < I0)) { V2=V1;I2=I1; V1=V0;I1=I0; V0=v;I0=j; }
            else if (v > V1 || (v == V1 && j < I1)) { V2=V1;I2=I1; V1=v;I1=j; }
            else if (v > V2 || (v == V2 && j < I2)) { V2=v;I2=j; }
        };
#pragma unroll
        for (int ww = 0; ww < 4; ww++)
#pragma unroll
            for (int hf = 0; hf < 2; hf++)
#pragma unroll
                for (int qq = 0; qq < 3; qq++)
                    ins(tvs[ww][hf][hh][qq], tjs[ww][hf][hh][qq]);
#pragma unroll
        for (int z = 1; z <= 3; z++) {
            int jz = i + z;
            if (jz < LL) ins(0.0f, jz);   // masked zeros (index-asc ties)
        }
        const int bh = hh * BB + b;
        const int rg = bh * LL + i;
        int sel[3] = {I0, I1, I2};
#pragma unroll
        for (int s = 0; s < 3; s++) {
            int t = sel[s];
            if (t <= i) {
                int p = atomicAdd(&g_cnt[rg], 1);
                if (p < CAP) g_list[rg * CAP + p] = t;
            } else {
                int tg = bh * LL + t;
                int p = atomicAdd(&g_cnt[tg], 1);
                if (p < CAP) g_list[tg * CAP + p] = i;
            }
        }
    }
}

// ---------------------------------------------------------------------------
// Stage 3 (fused sparse gather + LayerNorm): UNCHANGED R13.
// ---------------------------------------------------------------------------
__global__ void k_gather_ln(const float* __restrict__ tm,
                            const float* __restrict__ gam,
                            const float* __restrict__ bet,
                            float* __restrict__ out_ln,
                            float* __restrict__ out_tio)
{
    const int i = blockIdx.x, b = blockIdx.y;
    const int tid = threadIdx.x;
    const int h = tid >> 5, lane = tid & 31;
    const int bh = h * BB + b;
    const int rg = bh * LL + i;

    __shared__ unsigned bm[HH][7];
    __shared__ float red[4];

    if (lane < 7) bm[h][lane] = 0u;
    __syncwarp();

    const int n = min(g_cnt[rg], CAP);
    for (int c = lane; c < n; c += 32) {
        int j = g_list[rg * CAP + c];
        atomicOr(&bm[h][j >> 5], 1u << (j & 31));
    }
    __syncwarp();

    float ao = 0.f, at = 0.f;
    float ao2 = 0.f, at2 = 0.f;
    const float* rrow = g_raw + (size_t)rg * LL;
    const float* tmb  = tm + (size_t)(b * LL + i) * LL * DD + h * HS + lane;
    const float* svb  = g_sv + (size_t)bh * LL * HS + lane;

    for (int w = 0; w < 7; w++) {
        unsigned m = bm[h][w];
        while (m) {
            int b1 = __ffs(m) - 1;  m &= m - 1;
            int b2 = -1;
            if (m) { b2 = __ffs(m) - 1; m &= m - 1; }
            int ja = w * 32 + b1;
            float sga = rrow[ja];
            float sv_a = svb[ja * HS];
            float tm_a = tmb[(size_t)ja * DD];
            if (b2 >= 0) {
                int jb2 = w * 32 + b2;
                float sgb = rrow[jb2];
                ao2 += sgb * svb[jb2 * HS];
                at2 += sgb * tmb[(size_t)jb2 * DD];
            }
            ao += sga * sv_a;
            at += sga * tm_a;
        }
    }
    ao += ao2;
    at += at2;

    const int d = tid;                 // d = h*HS + lane
    out_tio[(b * LL + i) * DD + d] = at;

    // LayerNorm over the 128 'ao' values
    float s = ao;
#pragma unroll
    for (int k = 16; k; k >>= 1) s += __shfl_xor_sync(0xffffffffu, s, k);
    if (lane == 0) red[h] = s;
    __syncthreads();
    float mu = (red[0] + red[1] + red[2] + red[3]) * (1.f / 128.f);
    __syncthreads();

    float dv = ao - mu;
    float s2 = dv * dv;
#pragma unroll
    for (int k = 16; k; k >>= 1) s2 += __shfl_xor_sync(0xffffffffu, s2, k);
    if (lane == 0) red[h] = s2;
    __syncthreads();
    float var = (red[0] + red[1] + red[2] + red[3]) * (1.f / 128.f);

    out_ln[(b * LL + i) * DD + d] = dv / sqrtf(var + 1e-8f) * gam[d] + bet[d];
}

// ---------------------------------------------------------------------------
extern "C" void kernel_launch(void* const* d_in, const int* in_sizes, int n_in,
                              void* d_out, int out_size)
{
    const float* seqs = (const float*)d_in[0];
    // d_in[1] = attention_mask (known causal triu) — unused
    const float* tm   = (const float*)d_in[2];
    const float* w1   = (const float*)d_in[3];
    const float* b1   = (const float*)d_in[4];
    const float* w2   = (const float*)d_in[5];
    const float* b2   = (const float*)d_in[6];
    const float* w3   = (const float*)d_in[7];
    const float* b3   = (const float*)d_in[8];
    const float* lng  = (const float*)d_in[9];
    const float* lnb  = (const float*)d_in[10];

    float* out_ln  = (float*)d_out;
    float* out_tio = out_ln + BB * LL * DD;

    k_gemm     <<<dim3(50, 16), 64>>>(seqs, w1, b1, w2, b2);
    k_rawtop   <<<1650,        128>>>(tm, seqs, w3, b3);
    k_gather_ln<<<dim3(LL, BB),128>>>(tm, lng, lnb, out_ln, out_tio);
}

// round 16
// speedup vs baseline: 1.1071x; 1.0108x over previous
#include <cuda_runtime.h>
#include <cstdint>

// Problem constants
#define BB   8
#define LL   200
#define DD   128
#define HH   4
#define HS   32
#define HB   (HH*BB)        // 32
#define NROW (HB*LL)        // 6400

// Scratch (device globals; no allocation allowed)
__device__ float    g_ad[BB*LL*DD];    // a in [b][i][d]
__device__ float    g_bd[BB*LL*DD];    // b in [b][j][d]
__device__ float    g_sv[HB*LL*HS];    // sv in [bh][j][hs]
__device__ float    g_raw[NROW*LL];    // only j<=i valid
__device__ unsigned g_bm[NROW*7];      // 200-bit symmetrized mask per row

// ---------------------------------------------------------------------------
// Stage 1: a/b projections (sv lives in k_rawtop's grid). R13-exact tile:
// grid (50 rowtiles of 32, 8 = 2 matrices x 4 coltiles of 32), block 64.
// Tile 32x32, 4x4/thread (2.0 smem B/FFMA — best measured). Full-K
// XOR-swizzled smem, conflict-free STS + LDS.128. Per-output FMA chain =
// serial k -> a/b BIT-IDENTICAL to R13-passing. Also zeroes g_bm.
// ---------------------------------------------------------------------------
__global__ void __launch_bounds__(64) k_gemm(
                       const float* __restrict__ seqs,
                       const float* __restrict__ w1, const float* __restrict__ b1,
                       const float* __restrict__ w2, const float* __restrict__ b2)
{
    __shared__ float st[128 * 32];   // [k][r swizzled] 16 KB
    __shared__ float wt[128 * 32];   // [k][c swizzled] 16 KB

    const int ct = blockIdx.y;
    const int m  = ct >> 2;                 // matrix 0..1
    const int o0 = (ct & 3) * 32;           // col base within matrix
    const float* w    = (m == 0) ? w1 : w2;
    const float* bias = (m == 0) ? b1 : b2;

    const int row0 = blockIdx.x * 32;
    const int tid  = threadIdx.x;

    {
        int idx = (blockIdx.y * 50 + blockIdx.x) * 64 + tid;   // 0..25599
        g_bm[idx] = 0u;
        int idx2 = idx + 25600;
        if (idx2 < NROW * 7) g_bm[idx2] = 0u;
    }

    // Stage seqs tile: lane owns row r = idx&31 -> conflict-free STS.
#pragma unroll
    for (int it = 0; it < 16; it++) {
        int idx = it * 64 + tid;
        int r = idx & 31, k = (idx >> 5) * 4;
        float4 v = *(const float4*)&seqs[(row0 + r) * DD + k];
        st[(k + 0) * 32 + (r ^ (((k + 0) & 7) << 2))] = v.x;
        st[(k + 1) * 32 + (r ^ (((k + 1) & 7) << 2))] = v.y;
        st[(k + 2) * 32 + (r ^ (((k + 2) & 7) << 2))] = v.z;
        st[(k + 3) * 32 + (r ^ (((k + 3) & 7) << 2))] = v.w;
    }
#pragma unroll
    for (int it = 0; it < 16; it++) {
        int idx = it * 64 + tid;
        int c = idx & 31, k = (idx >> 5) * 4;
        float4 v = *(const float4*)&w[(o0 + c) * DD + k];
        wt[(k + 0) * 32 + (c ^ (((k + 0) & 7) << 2))] = v.x;
        wt[(k + 1) * 32 + (c ^ (((k + 1) & 7) << 2))] = v.y;
        wt[(k + 2) * 32 + (c ^ (((k + 2) & 7) << 2))] = v.z;
        wt[(k + 3) * 32 + (c ^ (((k + 3) & 7) << 2))] = v.w;
    }
    __syncthreads();

    const int rg = tid >> 3;       // 0..7
    const int cg = tid & 7;        // 0..7
    const int r0 = rg * 4, c0 = cg * 4;

    float acc[4][4];
#pragma unroll
    for (int r = 0; r < 4; r++)
#pragma unroll
        for (int c = 0; c < 4; c++) acc[r][c] = 0.f;

#pragma unroll 8
    for (int k = 0; k < DD; k++) {
        const int sw = (k & 7) << 2;
        float4 s4 = *(const float4*)&st[k * 32 + (r0 ^ sw)];
        float4 w4 = *(const float4*)&wt[k * 32 + (c0 ^ sw)];
        float sv[4] = {s4.x, s4.y, s4.z, s4.w};
        float wv[4] = {w4.x, w4.y, w4.z, w4.w};
#pragma unroll
        for (int r = 0; r < 4; r++)
#pragma unroll
            for (int c = 0; c < 4; c++)
                acc[r][c] += sv[r] * wv[c];
    }

    float bi[4];
#pragma unroll
    for (int c = 0; c < 4; c++) bi[c] = bias[o0 + c0 + c];

    float* dst = (m == 0) ? g_ad : g_bd;
#pragma unroll
    for (int r = 0; r < 4; r++) {
        int n = row0 + r0 + r;
        float4 v = {acc[r][0] + bi[0], acc[r][1] + bi[1],
                    acc[r][2] + bi[2], acc[r][3] + bi[3]};
        *(float4*)&dst[n * DD + o0 + c0] = v;
    }
}

// ---------------------------------------------------------------------------
// Stage 2: heterogeneous grid, 1D 1650 blocks x 128 threads.
//   blocks 0..1599    : rawtop for (b,i), i = (29*bx2) mod 200 scramble.
//                       tm via __ldcs. EXACT R13-passing arithmetic.
//                       Selections pushed DIRECTLY into g_bm via atomicOr
//                       (order-independent -> deterministic; same set as
//                       the old list scheme).
//   blocks 1600..1649 : sv projection — at the grid TAIL so rawtop's DRAM
//                       phase ramps first; sv fills triangle-tail bubbles.
// ---------------------------------------------------------------------------
__global__ void __launch_bounds__(128) k_rawtop(
    const float* __restrict__ tm,
    const float* __restrict__ seqs,
    const float* __restrict__ w3, const float* __restrict__ b3)
{
    __shared__ float s_seq[32 * DD];     // 16 KB (sv blocks)
    __shared__ float tvs[4][2][HH][3];
    __shared__ int   tjs[4][2][HH][3];

    const int bx = blockIdx.x;
    const int tid = threadIdx.x;

    if (bx >= 1600) {
        // ---- sv projection block: rows row0..row0+31, all 128 cols ----
        const int row0 = (bx - 1600) * 32;
#pragma unroll
        for (int it = 0; it < 32; it++) {
            int idx = it * 128 + tid;
            int r = idx >> 7, k = idx & 127;
            s_seq[r * DD + k] = seqs[(row0 + r) * DD + k];
        }
        __syncthreads();

        const int o = tid;
        const float bb = b3[o];
        float acc[32];
#pragma unroll
        for (int r = 0; r < 32; r++) acc[r] = 0.f;

        const float4* w4 = (const float4*)(w3 + o * DD);
        for (int k4 = 0; k4 < 32; k4++) {
            float4 wv = w4[k4];
#pragma unroll
            for (int r = 0; r < 32; r++) {
                float4 s4 = *(const float4*)&s_seq[r * DD + k4 * 4];
                acc[r] += s4.x * wv.x + s4.y * wv.y + s4.z * wv.z + s4.w * wv.w;
            }
        }

        const int h = o >> 5, hs = o & 31;
#pragma unroll
        for (int r = 0; r < 32; r++) {
            int n = row0 + r;
            int b_ = n / LL, i_ = n % LL;
            g_sv[((h * BB + b_) * LL + i_) * HS + hs] = acc[r] + bb;
        }
        return;
    }

    // ---- rawtop block ----
    const int b   = bx / LL;
    const int bx2 = bx % LL;
    const int i   = (29 * bx2) % LL;    // load-balance scramble
    const int w = tid >> 5, lane = tid & 31;
    const int half = lane >> 4;
    const int sub  = lane & 15;
    const int h    = sub >> 2;
    const int d0   = sub * 8;

    const float4* ap = (const float4*)(g_ad + (size_t)(b * LL + i) * DD + d0);
    const float4 aA = ap[0], aB = ap[1];
    float an = aA.x*aA.x + aA.y*aA.y + aA.z*aA.z + aA.w*aA.w
             + aB.x*aB.x + aB.y*aB.y + aB.z*aB.z + aB.w*aB.w;
    an += __shfl_xor_sync(0xffffffffu, an, 1);
    an += __shfl_xor_sync(0xffffffffu, an, 2);
    an = sqrtf(an);

    float v0 = -3.4e38f, v1 = -3.4e38f, v2 = -3.4e38f;
    int   j0 = -1, j1 = -1, j2 = -1;

    const float* tmp = tm   + (size_t)(b * LL + i) * LL * DD + d0;
    const float* bp  = g_bd + (size_t)b * LL * DD + d0;
    float* rr = g_raw + (size_t)((h * BB + b) * LL + i) * LL;

    for (int jb = 2 * w; jb <= i; jb += 16) {
        const int jA = jb + half;
        const int jB = jb + 8 + half;
        const bool pA = (jA <= i);
        const bool pB = (jB <= i);

        float numA = 0.f, denA = 0.f, numB = 0.f, denB = 0.f;

        if (pA) {
            const float4* t4 = (const float4*)(tmp + (size_t)jA * DD);
            const float4* b4 = (const float4*)(bp  + (size_t)jA * DD);
            float4 t0 = __ldcs(t4), t1 = __ldcs(t4 + 1);
            float4 c0v = b4[0], c1 = b4[1];
            float sx = t0.x + c0v.x, sy = t0.y + c0v.y, sz = t0.z + c0v.z, sw = t0.w + c0v.w;
            numA = aA.x*sx + aA.y*sy + aA.z*sz + aA.w*sw;
            denA = sx*sx + sy*sy + sz*sz + sw*sw;
            sx = t1.x + c1.x; sy = t1.y + c1.y; sz = t1.z + c1.z; sw = t1.w + c1.w;
            numA += aB.x*sx + aB.y*sy + aB.z*sz + aB.w*sw;
            denA += sx*sx + sy*sy + sz*sz + sw*sw;
        }
        if (pB) {
            const float4* t4 = (const float4*)(tmp + (size_t)jB * DD);
            const float4* b4 = (const float4*)(bp  + (size_t)jB * DD);
            float4 t0 = __ldcs(t4), t1 = __ldcs(t4 + 1);
            float4 c0v = b4[0], c1 = b4[1];
            float sx = t0.x + c0v.x, sy = t0.y + c0v.y, sz = t0.z + c0v.z, sw = t0.w + c0v.w;
            numB = aA.x*sx + aA.y*sy + aA.z*sz + aA.w*sw;
            denB = sx*sx + sy*sy + sz*sz + sw*sw;
            sx = t1.x + c1.x; sy = t1.y + c1.y; sz = t1.z + c1.z; sw = t1.w + c1.w;
            numB += aB.x*sx + aB.y*sy + aB.z*sz + aB.w*sw;
            denB += sx*sx + sy*sy + sz*sz + sw*sw;
        }

        numA += __shfl_xor_sync(0xffffffffu, numA, 1);
        denA += __shfl_xor_sync(0xffffffffu, denA, 1);
        numB += __shfl_xor_sync(0xffffffffu, numB, 1);
        denB += __shfl_xor_sync(0xffffffffu, denB, 1);
        numA += __shfl_xor_sync(0xffffffffu, numA, 2);
        denA += __shfl_xor_sync(0xffffffffu, denA, 2);
        numB += __shfl_xor_sync(0xffffffffu, numB, 2);
        denB += __shfl_xor_sync(0xffffffffu, denB, 2);

        if ((lane & 3) == 0) {
            if (pA) {
                float v = numA / (an * sqrtf(denA) + 1e-6f);
                rr[jA] = v;
                if (v > v0)      { v2=v1; j2=j1; v1=v0; j1=j0; v0=v; j0=jA; }
                else if (v > v1) { v2=v1; j2=j1; v1=v;  j1=jA; }
                else if (v > v2) { v2=v;  j2=jA; }
            }
            if (pB) {
                float v = numB / (an * sqrtf(denB) + 1e-6f);
                rr[jB] = v;
                if (v > v0)      { v2=v1; j2=j1; v1=v0; j1=j0; v0=v; j0=jB; }
                else if (v > v1) { v2=v1; j2=j1; v1=v;  j1=jB; }
                else if (v > v2) { v2=v;  j2=jB; }
            }
        }
    }

    if ((lane & 3) == 0) {
        tvs[w][half][h][0] = v0; tjs[w][half][h][0] = j0;
        tvs[w][half][h][1] = v1; tjs[w][half][h][1] = j1;
        tvs[w][half][h][2] = v2; tjs[w][half][h][2] = j2;
    }
    __syncthreads();

    // merge + direct bitmask push: thread hh < 4 handles head hh
    if (tid < HH) {
        const int hh = tid;
        float V0 = -3.4e38f, V1 = -3.4e38f, V2 = -3.4e38f;
        int   I0 = 0x7fffffff, I1 = 0x7fffffff, I2 = 0x7fffffff;
        auto ins = [&](float v, int j) {
            if (j < 0) return;
            if (v > V0 || (v == V0 && j < I0)) { V2=V1;I2=I1; V1=V0;I1=I0; V0=v;I0=j; }
            else if (v > V1 || (v == V1 && j < I1)) { V2=V1;I2=I1; V1=v;I1=j; }
            else if (v > V2 || (v == V2 && j < I2)) { V2=v;I2=j; }
        };
#pragma unroll
        for (int ww = 0; ww < 4; ww++)
#pragma unroll
            for (int hf = 0; hf < 2; hf++)
#pragma unroll
                for (int qq = 0; qq < 3; qq++)
                    ins(tvs[ww][hf][hh][qq], tjs[ww][hf][hh][qq]);
#pragma unroll
        for (int z = 1; z <= 3; z++) {
            int jz = i + z;
            if (jz < LL) ins(0.0f, jz);   // masked zeros (index-asc ties)
        }
        const int bh = hh * BB + b;
        const int rg = bh * LL + i;
        int sel[3] = {I0, I1, I2};
#pragma unroll
        for (int s = 0; s < 3; s++) {
            int t = sel[s];
            if (t <= i) {
                atomicOr(&g_bm[rg * 7 + (t >> 5)], 1u << (t & 31));
            } else {
                int tg = bh * LL + t;
                atomicOr(&g_bm[tg * 7 + (i >> 5)], 1u << (i & 31));
            }
        }
    }
}

// ---------------------------------------------------------------------------
// Stage 3 (fused sparse gather + LayerNorm): block per (b,i), warp = head.
// Mask read DIRECTLY from g_bm (no list indirection). Paired bit extraction
// for MLP; ascending-j iteration (deterministic, same set as R13).
// ---------------------------------------------------------------------------
__global__ void k_gather_ln(const float* __restrict__ tm,
                            const float* __restrict__ gam,
                            const float* __restrict__ bet,
                            float* __restrict__ out_ln,
                            float* __restrict__ out_tio)
{
    const int i = blockIdx.x, b = blockIdx.y;
    const int tid = threadIdx.x;
    const int h = tid >> 5, lane = tid & 31;
    const int bh = h * BB + b;
    const int rg = bh * LL + i;

    __shared__ unsigned bm[HH][7];
    __shared__ float red[4];

    if (lane < 7) bm[h][lane] = g_bm[rg * 7 + lane];
    __syncwarp();

    float ao = 0.f, at = 0.f;
    float ao2 = 0.f, at2 = 0.f;
    const float* rrow = g_raw + (size_t)rg * LL;
    const float* tmb  = tm + (size_t)(b * LL + i) * LL * DD + h * HS + lane;
    const float* svb  = g_sv + (size_t)bh * LL * HS + lane;

    for (int w = 0; w < 7; w++) {
        unsigned m = bm[h][w];
        while (m) {
            int b1 = __ffs(m) - 1;  m &= m - 1;
            int b2 = -1;
            if (m) { b2 = __ffs(m) - 1; m &= m - 1; }
            int ja = w * 32 + b1;
            float sga = rrow[ja];
            float sv_a = svb[ja * HS];
            float tm_a = tmb[(size_t)ja * DD];
            if (b2 >= 0) {
                int jb2 = w * 32 + b2;
                float sgb = rrow[jb2];
                ao2 += sgb * svb[jb2 * HS];
                at2 += sgb * tmb[(size_t)jb2 * DD];
            }
            ao += sga * sv_a;
            at += sga * tm_a;
        }
    }
    ao += ao2;
    at += at2;

    const int d = tid;                 // d = h*HS + lane
    out_tio[(b * LL + i) * DD + d] = at;

    // LayerNorm over the 128 'ao' values
    float s = ao;
#pragma unroll
    for (int k = 16; k; k >>= 1) s += __shfl_xor_sync(0xffffffffu, s, k);
    if (lane == 0) red[h] = s;
    __syncthreads();
    float mu = (red[0] + red[1] + red[2] + red[3]) * (1.f / 128.f);
    __syncthreads();

    float dv = ao - mu;
    float s2 = dv * dv;
#pragma unroll
    for (int k = 16; k; k >>= 1) s2 += __shfl_xor_sync(0xffffffffu, s2, k);
    if (lane == 0) red[h] = s2;
    __syncthreads();
    float var = (red[0] + red[1] + red[2] + red[3]) * (1.f / 128.f);

    out_ln[(b * LL + i) * DD + d] = dv / sqrtf(var + 1e-8f) * gam[d] + bet[d];
}

// ---------------------------------------------------------------------------
extern "C" void kernel_launch(void* const* d_in, const int* in_sizes, int n_in,
                              void* d_out, int out_size)
{
    const float* seqs = (const float*)d_in[0];
    // d_in[1] = attention_mask (known causal triu) — unused
    const float* tm   = (const float*)d_in[2];
    const float* w1   = (const float*)d_in[3];
    const float* b1   = (const float*)d_in[4];
    const float* w2   = (const float*)d_in[5];
    const float* b2   = (const float*)d_in[6];
    const float* w3   = (const float*)d_in[7];
    const float* b3   = (const float*)d_in[8];
    const float* lng  = (const float*)d_in[9];
    const float* lnb  = (const float*)d_in[10];

    float* out_ln  = (float*)d_out;
    float* out_tio = out_ln + BB * LL * DD;

    k_gemm     <<<dim3(50, 8),  64>>>(seqs, w1, b1, w2, b2);
    k_rawtop   <<<1650,        128>>>(tm, seqs, w3, b3);
    k_gather_ln<<<dim3(LL, BB),128>>>(tm, lng, lnb, out_ln, out_tio);
}